// round 15
// baseline (speedup 1.0000x reference)
#include <cuda_runtime.h>
#include <cuda_fp16.h>
#include <cstdint>
#include <math.h>

#define N_NODES 40000
#define N_EDGES 160000
#define DIN 64
#define D 32
#define EIN 16
#define EH 128
#define STEPS 3
#define EPS_BN 1e-5f

// ---------------- device scratch (no allocation allowed) ----------------
__device__ float g_h[N_NODES * D];                  // node features / GRU hidden
__device__ uint32_t g_theta[(size_t)N_EDGES * 512]; // per-edge mats, fp16 pairs (327 MB)
__device__ float g_agg[N_NODES * D];                // scatter-add accumulator
__device__ uint2 g_Bh[8 * 4096];                    // fp16 W2^T, fragment-native (256 KB)
__device__ __half g_Wcat[128 * 32];                 // [W_hh(96) | root^T(32)] fp16
__device__ __half g_Wih[96 * 32];                   // W_ih fp16
__device__ __half g_W1h[128 * 16];                  // fp16 W1' = W1 * bn-scale, [n][k]
__device__ float g_b1f[128];                        // folded edge-hidden bias

__device__ __forceinline__ void mma_f16_16x8x16(float c[4], const uint32_t a[4],
                                                uint32_t b0, uint32_t b1) {
    asm volatile(
        "mma.sync.aligned.m16n8k16.row.col.f32.f16.f16.f32 "
        "{%0,%1,%2,%3}, {%4,%5,%6,%7}, {%8,%9}, {%0,%1,%2,%3};"
        : "+f"(c[0]), "+f"(c[1]), "+f"(c[2]), "+f"(c[3])
        : "r"(a[0]), "r"(a[1]), "r"(a[2]), "r"(a[3]), "r"(b0), "r"(b1));
}

__device__ __forceinline__ uint32_t smem_u32(const void* p) {
    uint32_t a;
    asm("{ .reg .u64 t; cvta.to.shared.u64 t, %1; cvt.u32.u64 %0, t; }" : "=r"(a) : "l"(p));
    return a;
}
#define CP_ASYNC16(dst_u32, src_ptr) \
    asm volatile("cp.async.cg.shared.global [%0], [%1], 16;" :: "r"(dst_u32), "l"(src_ptr))
#define CP_COMMIT() asm volatile("cp.async.commit_group;")
#define CP_WAIT0() asm volatile("cp.async.wait_group 0;")
#define CP_WAIT1() asm volatile("cp.async.wait_group 1;")
#define BAR_PAIR(id) asm volatile("bar.sync %0, %1;" :: "r"(id), "r"(64) : "memory")

__device__ __forceinline__ uint32_t pack_h2(float a, float b) {
    __half2 h = __floats2half2_rn(a, b);
    return *reinterpret_cast<uint32_t*>(&h);
}

// fast sigmoid/tanh via MUFU (EX2 + RCP); ~2-3 ulp, negligible vs fp16 path err
__device__ __forceinline__ float fsig(float x) {
    return __fdividef(1.f, 1.f + __expf(-x));
}
__device__ __forceinline__ float ftanh(float x) {
    return 2.f * fsig(2.f * x) - 1.f;
}

// ---------------- K_pre: fused prepB + prepW + proj (independent work) ------
// blocks [0,5000): proj (8 nodes each) ; [5000,5128): prepB ; 5128: prepW
__global__ void __launch_bounds__(256) k_pre(
    const float* __restrict__ x, const float* __restrict__ W,
    const float* __restrict__ b, const float* __restrict__ g,
    const float* __restrict__ bb, const float* __restrict__ eW2,
    const float* __restrict__ W_hh, const float* __restrict__ root,
    const float* __restrict__ W_ih, const float* __restrict__ eW1,
    const float* __restrict__ eb1, const float* __restrict__ bn2_g,
    const float* __restrict__ bn2_b) {
    __shared__ float Ws[DIN * D];
    const int blk = blockIdx.x;
    const int tid = threadIdx.x;

    if (blk < 5000) {
        for (int i = tid; i < DIN * D; i += 256) Ws[i] = W[i];
        __syncthreads();
        int lane = tid & 31;
        int node = blk * 8 + (tid >> 5);
        if (node >= N_NODES) return;
        float x0 = x[node * DIN + lane];
        float x1 = x[node * DIN + 32 + lane];
        float acc = 0.f;
#pragma unroll
        for (int i = 0; i < 32; i++) {
            acc = fmaf(__shfl_sync(0xffffffffu, x0, i), Ws[i * D + lane], acc);
            acc = fmaf(__shfl_sync(0xffffffffu, x1, i), Ws[(32 + i) * D + lane], acc);
        }
        float s = g[lane] * rsqrtf(1.f + EPS_BN);
        float v = (acc + b[lane]) * s + bb[lane];
        g_h[node * D + lane] = fmaxf(v, 0.f);
        g_agg[node * D + lane] = 0.f;
    } else if (blk < 5128) {
        int j = (blk - 5000) * 256 + tid;
        int p = j >> 12, r = j & 4095;
        int ks = r >> 9, ntg = (r >> 5) & 15, lane = r & 31;
        int lq = lane >> 2, lr = lane & 3;
        int n = p * 128 + ntg * 8 + lq;
        int k0 = ks * 16 + lr * 2;
        uint2 v;
        v.x = pack_h2(eW2[(size_t)k0 * 1024 + n], eW2[(size_t)(k0 + 1) * 1024 + n]);
        v.y = pack_h2(eW2[(size_t)(k0 + 8) * 1024 + n], eW2[(size_t)(k0 + 9) * 1024 + n]);
        g_Bh[j] = v;
    } else {
        for (int i = tid; i < 128 * 32; i += 256) {
            int n = i >> 5, k = i & 31;
            float v = (n < 96) ? W_hh[n * 32 + k] : root[k * 32 + (n - 96)];
            g_Wcat[i] = __float2half_rn(v);
        }
        for (int i = tid; i < 96 * 32; i += 256)
            g_Wih[i] = __float2half_rn(W_ih[i]);
        for (int i = tid; i < 128 * 16; i += 256) {
            int n = i >> 4, k = i & 15;
            float s = bn2_g[n] * rsqrtf(1.f + EPS_BN);
            g_W1h[i] = __float2half_rn(eW1[k * EH + n] * s);
        }
        if (tid < 128) {
            float s = bn2_g[tid] * rsqrtf(1.f + EPS_BN);
            g_b1f[tid] = eb1[tid] * s + bn2_b[tid];
        }
    }
}

// ---------------- K3: fused eh-MMA + theta GEMM (monolithic, v5) ------------
#define TH_AF 0
#define TH_B0 32768
#define TH_B1 65536
#define TH_STG 98304
#define TH_EA 98304
#define TH_W1 104448
#define TH_B1F 110592
#define TH_SMEM_TOTAL 114688

__global__ void __launch_bounds__(256, 2) k_theta(const float* __restrict__ eb2,
                                                  const float* __restrict__ ea) {
    extern __shared__ char smem[];
    uint4* AF = reinterpret_cast<uint4*>(smem + TH_AF);
    uint32_t* stg = reinterpret_cast<uint32_t*>(smem + TH_STG);
    __half* ea16 = reinterpret_cast<__half*>(smem + TH_EA);
    __half* w1s = reinterpret_cast<__half*>(smem + TH_W1);
    float* b1s = reinterpret_cast<float*>(smem + TH_B1F);
    const int tid = threadIdx.x, warp = tid >> 5, lane = tid & 31;
    const int lq = lane >> 2, lr = lane & 3;
    const int m0 = blockIdx.x * 128;
    const uint32_t sb = smem_u32(smem);
    const int wg = warp & 3;
    const int wh = warp >> 2;
    const int wn = wh * 64;

    {
        const char* src = reinterpret_cast<const char*>(g_Bh);
#pragma unroll
        for (int it = 0; it < 8; it++) {
            int idx = it * 256 + tid;
            CP_ASYNC16(sb + TH_B0 + idx * 16, src + idx * 16);
        }
        CP_COMMIT();
#pragma unroll
        for (int it = 0; it < 8; it++) {
            int idx = it * 256 + tid;
            CP_ASYNC16(sb + TH_B1 + idx * 16, src + 32768 + idx * 16);
        }
        CP_COMMIT();
    }

    {
        int row = tid >> 1, half8 = tid & 1;
        float4 v0 = *reinterpret_cast<const float4*>(&ea[(size_t)(m0 + row) * EIN + half8 * 8]);
        float4 v1 = *reinterpret_cast<const float4*>(&ea[(size_t)(m0 + row) * EIN + half8 * 8 + 4]);
        uint32_t* dst = reinterpret_cast<uint32_t*>(&ea16[row * 24 + half8 * 8]);
        dst[0] = pack_h2(v0.x, v0.y);
        dst[1] = pack_h2(v0.z, v0.w);
        dst[2] = pack_h2(v1.x, v1.y);
        dst[3] = pack_h2(v1.z, v1.w);
    }
    for (int i = tid; i < 128 * 8; i += 256) {
        int n = i >> 3, q = i & 7;
        reinterpret_cast<uint32_t*>(&w1s[n * 24])[q] =
            reinterpret_cast<const uint32_t*>(&g_W1h[n * 16])[q];
    }
    if (tid < 128) b1s[tid] = g_b1f[tid];
    __syncthreads();

    // eh pass: A = relu(ea @ W1' + b1'), K=16; write fragment-native AF
    {
        float c0[2][8][4];
#pragma unroll
        for (int mt = 0; mt < 2; mt++)
#pragma unroll
            for (int nt = 0; nt < 8; nt++)
#pragma unroll
                for (int i = 0; i < 4; i++) c0[mt][nt][i] = 0.f;
        uint32_t a[2][4];
#pragma unroll
        for (int mt = 0; mt < 2; mt++) {
            int r = wg * 32 + mt * 16 + lq;
            a[mt][0] = *reinterpret_cast<const uint32_t*>(&ea16[r * 24 + lr * 2]);
            a[mt][1] = *reinterpret_cast<const uint32_t*>(&ea16[(r + 8) * 24 + lr * 2]);
            a[mt][2] = *reinterpret_cast<const uint32_t*>(&ea16[r * 24 + lr * 2 + 8]);
            a[mt][3] = *reinterpret_cast<const uint32_t*>(&ea16[(r + 8) * 24 + lr * 2 + 8]);
        }
#pragma unroll
        for (int nt = 0; nt < 8; nt++) {
            int n = wn + nt * 8 + lq;
            uint32_t b0 = *reinterpret_cast<const uint32_t*>(&w1s[n * 24 + lr * 2]);
            uint32_t b1 = *reinterpret_cast<const uint32_t*>(&w1s[n * 24 + lr * 2 + 8]);
            mma_f16_16x8x16(c0[0][nt], a[0], b0, b1);
            mma_f16_16x8x16(c0[1][nt], a[1], b0, b1);
        }
#pragma unroll
        for (int mt = 0; mt < 2; mt++) {
#pragma unroll
            for (int t = 0; t < 4; t++) {
                int nt0 = 2 * t, nt1 = 2 * t + 1;
                int col0 = wn + nt0 * 8 + lr * 2;
                int col1 = wn + nt1 * 8 + lr * 2;
                float b00 = b1s[col0], b01 = b1s[col0 + 1];
                float b10 = b1s[col1], b11 = b1s[col1 + 1];
                uint4 u;
                u.x = pack_h2(fmaxf(c0[mt][nt0][0] + b00, 0.f), fmaxf(c0[mt][nt0][1] + b01, 0.f));
                u.y = pack_h2(fmaxf(c0[mt][nt0][2] + b00, 0.f), fmaxf(c0[mt][nt0][3] + b01, 0.f));
                u.z = pack_h2(fmaxf(c0[mt][nt1][0] + b10, 0.f), fmaxf(c0[mt][nt1][1] + b11, 0.f));
                u.w = pack_h2(fmaxf(c0[mt][nt1][2] + b10, 0.f), fmaxf(c0[mt][nt1][3] + b11, 0.f));
                int mg = wg * 2 + mt;
                int ks = wh * 4 + t;
                AF[(mg * 8 + ks) * 32 + lane] = u;
            }
        }
    }
    CP_WAIT1();
    __syncthreads();

    const int mg0 = wg * 2;
    const int pairbar = 1 + wg;

#pragma unroll 1
    for (int p = 0; p < 8; p++) {
        const uint2* Bs = reinterpret_cast<const uint2*>(smem + ((p & 1) ? TH_B1 : TH_B0));

        float c[2][8][4];
#pragma unroll
        for (int mt = 0; mt < 2; mt++)
#pragma unroll
            for (int nt = 0; nt < 8; nt++)
#pragma unroll
                for (int i = 0; i < 4; i++) c[mt][nt][i] = 0.f;

#pragma unroll
        for (int ks = 0; ks < 8; ks++) {
            uint4 ua0 = AF[(mg0 * 8 + ks) * 32 + lane];
            uint4 ua1 = AF[((mg0 + 1) * 8 + ks) * 32 + lane];
            uint32_t a0[4] = {ua0.x, ua0.y, ua0.z, ua0.w};
            uint32_t a1[4] = {ua1.x, ua1.y, ua1.z, ua1.w};
#pragma unroll
            for (int nt = 0; nt < 8; nt++) {
                uint2 vb = Bs[(ks * 16 + wh * 8 + nt) * 32 + lane];
                mma_f16_16x8x16(c[0][nt], a0, vb.x, vb.y);
                mma_f16_16x8x16(c[1][nt], a1, vb.x, vb.y);
            }
        }

        // epilogue first (pair-local), overlapping the p+1 prefetch
#pragma unroll
        for (int mt = 0; mt < 2; mt++) {
#pragma unroll
            for (int nt = 0; nt < 8; nt++) {
                int col = wn + nt * 8 + lr * 2;
                float2 bv = __ldg(reinterpret_cast<const float2*>(&eb2[p * 128 + col]));
                uint32_t h0 = pack_h2(c[mt][nt][0] + bv.x, c[mt][nt][1] + bv.y);
                uint32_t h1 = pack_h2(c[mt][nt][2] + bv.x, c[mt][nt][3] + bv.y);
                int cch = wh * 8 + nt;
                int r0 = wg * 16 + lq;
                int r1 = r0 + 8;
                stg[r0 * 64 + ((cch ^ (r0 & 15)) << 2) + lr] = h0;
                stg[r1 * 64 + ((cch ^ (r1 & 15)) << 2) + lr] = h1;
            }
            BAR_PAIR(pairbar);
#pragma unroll
            for (int i = 0; i < 4; i++) {
                int idx = i * 32 + lane;
                int lrow8 = idx >> 4;
                int cch = idx & 15;
                int localRow = wg * 16 + wh * 8 + lrow8;
                uint4 v = *reinterpret_cast<const uint4*>(
                    &stg[localRow * 64 + ((cch ^ (localRow & 15)) << 2)]);
                int globalRow = m0 + wg * 32 + mt * 16 + wh * 8 + lrow8;
                reinterpret_cast<uint4*>(g_theta)[(size_t)globalRow * 128 + p * 16 + cch] = v;
            }
            BAR_PAIR(pairbar);
        }

        if (p < 7) CP_WAIT0();
        __syncthreads();

        if (p < 6) {
            uint32_t dstb = sb + ((p & 1) ? TH_B1 : TH_B0);
            const char* src = reinterpret_cast<const char*>(g_Bh) + (size_t)(p + 2) * 32768;
#pragma unroll
            for (int it = 0; it < 8; it++) {
                int idx = it * 256 + tid;
                CP_ASYNC16(dstb + idx * 16, src + idx * 16);
            }
            CP_COMMIT();
        }
    }
}

// ---------------- K5: msg = h[src] @ theta_e ; atomic scatter (uint4) -------
__global__ void __launch_bounds__(256) k_msg(const int* __restrict__ ei) {
    int gw = (blockIdx.x * blockDim.x + threadIdx.x) >> 5;
    if (gw >= N_EDGES) return;
    int lane = threadIdx.x & 31;
    int src = __ldg(&ei[gw]);
    int dst = __ldg(&ei[N_EDGES + gw]);
    float hv = g_h[src * D + lane];
    const uint4* th4 = reinterpret_cast<const uint4*>(g_theta + (size_t)gw * 512);
    const int colg = lane & 3;
    const int rbase = lane >> 2;
    float acc[8];
#pragma unroll
    for (int j = 0; j < 8; j++) acc[j] = 0.f;
#pragma unroll
    for (int it = 0; it < 4; it++) {
        int row = it * 8 + rbase;
        uint4 u = __ldcs(&th4[row * 4 + colg]);
        float hr = __shfl_sync(0xffffffffu, hv, row);
        float2 f0 = __half22float2(*reinterpret_cast<const __half2*>(&u.x));
        float2 f1 = __half22float2(*reinterpret_cast<const __half2*>(&u.y));
        float2 f2 = __half22float2(*reinterpret_cast<const __half2*>(&u.z));
        float2 f3 = __half22float2(*reinterpret_cast<const __half2*>(&u.w));
        acc[0] = fmaf(hr, f0.x, acc[0]); acc[1] = fmaf(hr, f0.y, acc[1]);
        acc[2] = fmaf(hr, f1.x, acc[2]); acc[3] = fmaf(hr, f1.y, acc[3]);
        acc[4] = fmaf(hr, f2.x, acc[4]); acc[5] = fmaf(hr, f2.y, acc[5]);
        acc[6] = fmaf(hr, f3.x, acc[6]); acc[7] = fmaf(hr, f3.y, acc[7]);
    }
#pragma unroll
    for (int m = 4; m <= 16; m <<= 1) {
#pragma unroll
        for (int j = 0; j < 8; j++)
            acc[j] += __shfl_xor_sync(0xffffffffu, acc[j], m);
    }
    if (lane < 4) {
        float* dp = &g_agg[dst * D + colg * 8];
#pragma unroll
        for (int j = 0; j < 8; j++) atomicAdd(dp + j, acc[j]);
    }
}

// ---------------- K6: conv + relu + GRU via HMMA, 2 tiles of 128 per block --
#define UP_H16 0
#define UP_M16 (UP_H16 + 9216)
#define UP_W1  (UP_M16 + 9216)
#define UP_W2  (UP_W1 + 9216)
#define UP_HF  (UP_W2 + 6912)
#define UP_BIH (UP_HF + 18432)
#define UP_BHH (UP_BIH + 384)
#define UP_CB  (UP_BHH + 384)
#define UP_SMEM_TOTAL (UP_CB + 128)

__global__ void __launch_bounds__(256) k_update(const float* __restrict__ cb,
                                                const float* __restrict__ b_ih,
                                                const float* __restrict__ b_hh,
                                                float* __restrict__ out,
                                                int write_out) {
    extern __shared__ char smem[];
    __half* h16 = reinterpret_cast<__half*>(smem + UP_H16);
    __half* m16 = reinterpret_cast<__half*>(smem + UP_M16);
    __half* w1 = reinterpret_cast<__half*>(smem + UP_W1);
    __half* w2 = reinterpret_cast<__half*>(smem + UP_W2);
    float* hf = reinterpret_cast<float*>(smem + UP_HF);
    float* sbih = reinterpret_cast<float*>(smem + UP_BIH);
    float* sbhh = reinterpret_cast<float*>(smem + UP_BHH);
    float* scb = reinterpret_cast<float*>(smem + UP_CB);
    const int tid = threadIdx.x, warp = tid >> 5, lane = tid & 31;
    const int lq = lane >> 2, lr = lane & 3;
    const int wm = warp * 16;

    for (int i = tid; i < 128 * 32; i += 256) {
        int n = i >> 5, k = i & 31;
        w1[n * 36 + k] = g_Wcat[i];
    }
    for (int i = tid; i < 96 * 32; i += 256) {
        int n = i >> 5, k = i & 31;
        w2[n * 36 + k] = g_Wih[i];
    }
    if (tid < 96) { sbih[tid] = b_ih[tid]; sbhh[tid] = b_hh[tid]; }
    if (tid < 32) scb[tid] = cb[tid];

#pragma unroll 1
    for (int t = 0; t < 2; t++) {
        const int node0 = (blockIdx.x * 2 + t) * 128;
        if (node0 >= N_NODES) break;

#pragma unroll
        for (int it = 0; it < 4; it++) {
            int idx = it * 256 + tid;
            int row = idx >> 3;
            int c4 = (idx & 7) << 2;
            int node = node0 + row;
            float4 v = make_float4(0.f, 0.f, 0.f, 0.f);
            if (node < N_NODES)
                v = *reinterpret_cast<const float4*>(&g_h[node * D + c4]);
            *reinterpret_cast<float4*>(&hf[row * 36 + c4]) = v;
            uint2 u = make_uint2(pack_h2(v.x, v.y), pack_h2(v.z, v.w));
            *reinterpret_cast<uint2*>(&h16[row * 36 + c4]) = u;
        }
        __syncthreads();

        float c1[16][4];
#pragma unroll
        for (int nt = 0; nt < 16; nt++)
#pragma unroll
            for (int i = 0; i < 4; i++) c1[nt][i] = 0.f;
#pragma unroll
        for (int ks = 0; ks < 2; ks++) {
            int kb = ks * 16 + lr * 2;
            uint32_t a[4];
            a[0] = *reinterpret_cast<const uint32_t*>(&h16[(wm + lq) * 36 + kb]);
            a[2] = *reinterpret_cast<const uint32_t*>(&h16[(wm + lq) * 36 + kb + 8]);
            a[1] = *reinterpret_cast<const uint32_t*>(&h16[(wm + lq + 8) * 36 + kb]);
            a[3] = *reinterpret_cast<const uint32_t*>(&h16[(wm + lq + 8) * 36 + kb + 8]);
#pragma unroll
            for (int nt = 0; nt < 16; nt++) {
                int n = nt * 8 + lq;
                uint32_t b0 = *reinterpret_cast<const uint32_t*>(&w1[n * 36 + kb]);
                uint32_t b1 = *reinterpret_cast<const uint32_t*>(&w1[n * 36 + kb + 8]);
                mma_f16_16x8x16(c1[nt], a, b0, b1);
            }
        }

        int rowA = wm + lq, rowB = wm + lq + 8;
        int nodeA = node0 + rowA, nodeB = node0 + rowB;
#pragma unroll
        for (int nt = 0; nt < 4; nt++) {
            int jp = nt * 8 + lr * 2;
            float cb0 = scb[jp], cb1 = scb[jp + 1];
            float2 agA = make_float2(0.f, 0.f), agB = make_float2(0.f, 0.f);
            if (nodeA < N_NODES) agA = *reinterpret_cast<const float2*>(&g_agg[nodeA * D + jp]);
            if (nodeB < N_NODES) agB = *reinterpret_cast<const float2*>(&g_agg[nodeB * D + jp]);
            float m0v = fmaxf(c1[12 + nt][0] + agA.x + cb0, 0.f);
            float m1v = fmaxf(c1[12 + nt][1] + agA.y + cb1, 0.f);
            float m2v = fmaxf(c1[12 + nt][2] + agB.x + cb0, 0.f);
            float m3v = fmaxf(c1[12 + nt][3] + agB.y + cb1, 0.f);
            *reinterpret_cast<uint32_t*>(&m16[rowA * 36 + jp]) = pack_h2(m0v, m1v);
            *reinterpret_cast<uint32_t*>(&m16[rowB * 36 + jp]) = pack_h2(m2v, m3v);
        }
        __syncthreads();

        float c2[12][4];
#pragma unroll
        for (int nt = 0; nt < 12; nt++)
#pragma unroll
            for (int i = 0; i < 4; i++) c2[nt][i] = 0.f;
#pragma unroll
        for (int ks = 0; ks < 2; ks++) {
            int kb = ks * 16 + lr * 2;
            uint32_t a[4];
            a[0] = *reinterpret_cast<const uint32_t*>(&m16[(wm + lq) * 36 + kb]);
            a[2] = *reinterpret_cast<const uint32_t*>(&m16[(wm + lq) * 36 + kb + 8]);
            a[1] = *reinterpret_cast<const uint32_t*>(&m16[(wm + lq + 8) * 36 + kb]);
            a[3] = *reinterpret_cast<const uint32_t*>(&m16[(wm + lq + 8) * 36 + kb + 8]);
#pragma unroll
            for (int nt = 0; nt < 12; nt++) {
                int n = nt * 8 + lq;
                uint32_t b0 = *reinterpret_cast<const uint32_t*>(&w2[n * 36 + kb]);
                uint32_t b1 = *reinterpret_cast<const uint32_t*>(&w2[n * 36 + kb + 8]);
                mma_f16_16x8x16(c2[nt], a, b0, b1);
            }
        }

#pragma unroll
        for (int nt = 0; nt < 4; nt++) {
            int jp = nt * 8 + lr * 2;
#pragma unroll
            for (int hrow = 0; hrow < 2; hrow++) {
                int node = hrow ? nodeB : nodeA;
                if (node >= N_NODES) continue;
                int rl = hrow ? rowB : rowA;
                float hn0, hn1;
                {
                    int ci = 2 * hrow;
                    float gr0 = c2[nt][ci] + sbih[jp] + c1[nt][ci] + sbhh[jp];
                    float gr1 = c2[nt][ci + 1] + sbih[jp + 1] + c1[nt][ci + 1] + sbhh[jp + 1];
                    float gz0 = c2[4 + nt][ci] + sbih[32 + jp] + c1[4 + nt][ci] + sbhh[32 + jp];
                    float gz1 = c2[4 + nt][ci + 1] + sbih[33 + jp] + c1[4 + nt][ci + 1] + sbhh[33 + jp];
                    float r0 = fsig(gr0);
                    float r1 = fsig(gr1);
                    float z0 = fsig(gz0);
                    float z1 = fsig(gz1);
                    float gn0 = c2[8 + nt][ci] + sbih[64 + jp];
                    float gn1 = c2[8 + nt][ci + 1] + sbih[65 + jp];
                    float ghn0 = c1[8 + nt][ci] + sbhh[64 + jp];
                    float ghn1 = c1[8 + nt][ci + 1] + sbhh[65 + jp];
                    float n0 = ftanh(gn0 + r0 * ghn0);
                    float n1 = ftanh(gn1 + r1 * ghn1);
                    float hv0 = hf[rl * 36 + jp];
                    float hv1 = hf[rl * 36 + jp + 1];
                    hn0 = (1.f - z0) * n0 + z0 * hv0;
                    hn1 = (1.f - z1) * n1 + z1 * hv1;
                }
                float2 hv2 = make_float2(hn0, hn1);
                *reinterpret_cast<float2*>(&g_h[node * D + jp]) = hv2;
                *reinterpret_cast<float2*>(&g_agg[node * D + jp]) = make_float2(0.f, 0.f);
                if (write_out)
                    *reinterpret_cast<float2*>(&out[node * D + jp]) = hv2;
            }
        }
        __syncthreads();  // protect hf/h16/m16 reuse by next tile
    }
}

// ---------------- launch ----------------
extern "C" void kernel_launch(void* const* d_in, const int* in_sizes, int n_in,
                              void* d_out, int out_size) {
    (void)in_sizes; (void)n_in; (void)out_size;
    const float* x        = (const float*)d_in[0];
    const int*   ei       = (const int*)d_in[1];
    const float* ea       = (const float*)d_in[2];
    const float* proj_W   = (const float*)d_in[3];
    const float* proj_b   = (const float*)d_in[4];
    const float* bn1_g    = (const float*)d_in[5];
    const float* bn1_b    = (const float*)d_in[6];
    const float* eW1      = (const float*)d_in[7];
    const float* eb1      = (const float*)d_in[8];
    const float* bn2_g    = (const float*)d_in[9];
    const float* bn2_b    = (const float*)d_in[10];
    const float* eW2      = (const float*)d_in[11];
    const float* eb2      = (const float*)d_in[12];
    const float* root     = (const float*)d_in[13];
    const float* cb       = (const float*)d_in[14];
    const float* W_ih     = (const float*)d_in[15];
    const float* W_hh     = (const float*)d_in[16];
    const float* b_ih     = (const float*)d_in[17];
    const float* b_hh     = (const float*)d_in[18];
    float* out = (float*)d_out;

    static int attr_set = 0;
    if (!attr_set) {
        cudaFuncSetAttribute(k_theta, cudaFuncAttributeMaxDynamicSharedMemorySize,
                             TH_SMEM_TOTAL);
        cudaFuncSetAttribute(k_update, cudaFuncAttributeMaxDynamicSharedMemorySize,
                             UP_SMEM_TOTAL);
        attr_set = 1;
    }

    // fused prologue: proj (5000 blocks) + prepB (128) + prepW (1)
    k_pre<<<5129, 256>>>(x, proj_W, proj_b, bn1_g, bn1_b, eW2,
                         W_hh, root, W_ih, eW1, eb1, bn2_g, bn2_b);
    k_theta<<<N_EDGES / 128, 256, TH_SMEM_TOTAL>>>(eb2, ea);

    for (int s = 0; s < STEPS; s++) {
        k_msg<<<N_EDGES * 32 / 256, 256>>>(ei);
        k_update<<<157, 256, UP_SMEM_TOTAL>>>(
            cb, b_ih, b_hh, out, s == STEPS - 1 ? 1 : 0);
    }
}

// round 16
// speedup vs baseline: 1.0507x; 1.0507x over previous
#include <cuda_runtime.h>
#include <cuda_fp16.h>
#include <cstdint>
#include <math.h>

#define N_NODES 40000
#define N_EDGES 160000
#define DIN 64
#define D 32
#define EIN 16
#define EH 128
#define STEPS 3
#define EPS_BN 1e-5f

// ---------------- device scratch (no allocation allowed) ----------------
__device__ float g_h[N_NODES * D];                  // node features / GRU hidden
__device__ uint32_t g_theta[(size_t)N_EDGES * 512]; // per-edge mats, fp16 pairs (327 MB)
__device__ float g_agg[N_NODES * D];                // scatter-add accumulator
__device__ uint2 g_Bh[8 * 4096];                    // fp16 W2^T, fragment-native (256 KB)
__device__ __half g_Wcat[128 * 32];                 // [W_hh(96) | root^T(32)] fp16
__device__ __half g_Wih[96 * 32];                   // W_ih fp16
__device__ __half g_W1h[128 * 16];                  // fp16 W1' = W1 * bn-scale, [n][k]
__device__ float g_b1f[128];                        // folded edge-hidden bias

__device__ __forceinline__ void mma_f16_16x8x16(float c[4], const uint32_t a[4],
                                                uint32_t b0, uint32_t b1) {
    asm volatile(
        "mma.sync.aligned.m16n8k16.row.col.f32.f16.f16.f32 "
        "{%0,%1,%2,%3}, {%4,%5,%6,%7}, {%8,%9}, {%0,%1,%2,%3};"
        : "+f"(c[0]), "+f"(c[1]), "+f"(c[2]), "+f"(c[3])
        : "r"(a[0]), "r"(a[1]), "r"(a[2]), "r"(a[3]), "r"(b0), "r"(b1));
}

__device__ __forceinline__ uint32_t smem_u32(const void* p) {
    uint32_t a;
    asm("{ .reg .u64 t; cvta.to.shared.u64 t, %1; cvt.u32.u64 %0, t; }" : "=r"(a) : "l"(p));
    return a;
}
#define CP_ASYNC16(dst_u32, src_ptr) \
    asm volatile("cp.async.cg.shared.global [%0], [%1], 16;" :: "r"(dst_u32), "l"(src_ptr))
#define CP_COMMIT() asm volatile("cp.async.commit_group;")
#define CP_WAIT0() asm volatile("cp.async.wait_group 0;")
#define CP_WAIT1() asm volatile("cp.async.wait_group 1;")
#define BAR_PAIR(id) asm volatile("bar.sync %0, %1;" :: "r"(id), "r"(64) : "memory")

__device__ __forceinline__ uint32_t pack_h2(float a, float b) {
    __half2 h = __floats2half2_rn(a, b);
    return *reinterpret_cast<uint32_t*>(&h);
}

// fast sigmoid/tanh via MUFU (EX2 + RCP)
__device__ __forceinline__ float fsig(float x) {
    return __fdividef(1.f, 1.f + __expf(-x));
}
__device__ __forceinline__ float ftanh(float x) {
    return 2.f * fsig(2.f * x) - 1.f;
}

// ---------------- K_pre: fused prepB + prepW + proj (independent work) ------
__global__ void __launch_bounds__(256) k_pre(
    const float* __restrict__ x, const float* __restrict__ W,
    const float* __restrict__ b, const float* __restrict__ g,
    const float* __restrict__ bb, const float* __restrict__ eW2,
    const float* __restrict__ W_hh, const float* __restrict__ root,
    const float* __restrict__ W_ih, const float* __restrict__ eW1,
    const float* __restrict__ eb1, const float* __restrict__ bn2_g,
    const float* __restrict__ bn2_b) {
    __shared__ float Ws[DIN * D];
    const int blk = blockIdx.x;
    const int tid = threadIdx.x;

    if (blk < 5000) {
        for (int i = tid; i < DIN * D; i += 256) Ws[i] = W[i];
        __syncthreads();
        int lane = tid & 31;
        int node = blk * 8 + (tid >> 5);
        if (node >= N_NODES) return;
        float x0 = x[node * DIN + lane];
        float x1 = x[node * DIN + 32 + lane];
        float acc = 0.f;
#pragma unroll
        for (int i = 0; i < 32; i++) {
            acc = fmaf(__shfl_sync(0xffffffffu, x0, i), Ws[i * D + lane], acc);
            acc = fmaf(__shfl_sync(0xffffffffu, x1, i), Ws[(32 + i) * D + lane], acc);
        }
        float s = g[lane] * rsqrtf(1.f + EPS_BN);
        float v = (acc + b[lane]) * s + bb[lane];
        g_h[node * D + lane] = fmaxf(v, 0.f);
        g_agg[node * D + lane] = 0.f;
    } else if (blk < 5128) {
        int j = (blk - 5000) * 256 + tid;
        int p = j >> 12, r = j & 4095;
        int ks = r >> 9, ntg = (r >> 5) & 15, lane = r & 31;
        int lq = lane >> 2, lr = lane & 3;
        int n = p * 128 + ntg * 8 + lq;
        int k0 = ks * 16 + lr * 2;
        uint2 v;
        v.x = pack_h2(eW2[(size_t)k0 * 1024 + n], eW2[(size_t)(k0 + 1) * 1024 + n]);
        v.y = pack_h2(eW2[(size_t)(k0 + 8) * 1024 + n], eW2[(size_t)(k0 + 9) * 1024 + n]);
        g_Bh[j] = v;
    } else {
        for (int i = tid; i < 128 * 32; i += 256) {
            int n = i >> 5, k = i & 31;
            float v = (n < 96) ? W_hh[n * 32 + k] : root[k * 32 + (n - 96)];
            g_Wcat[i] = __float2half_rn(v);
        }
        for (int i = tid; i < 96 * 32; i += 256)
            g_Wih[i] = __float2half_rn(W_ih[i]);
        for (int i = tid; i < 128 * 16; i += 256) {
            int n = i >> 4, k = i & 15;
            float s = bn2_g[n] * rsqrtf(1.f + EPS_BN);
            g_W1h[i] = __float2half_rn(eW1[k * EH + n] * s);
        }
        if (tid < 128) {
            float s = bn2_g[tid] * rsqrtf(1.f + EPS_BN);
            g_b1f[tid] = eb1[tid] * s + bn2_b[tid];
        }
    }
}

// ---------------- K3: fused eh-MMA + theta GEMM (monolithic, v5) ------------
#define TH_AF 0
#define TH_B0 32768
#define TH_B1 65536
#define TH_STG 98304
#define TH_EA 98304
#define TH_W1 104448
#define TH_B1F 110592
#define TH_SMEM_TOTAL 114688

__global__ void __launch_bounds__(256, 2) k_theta(const float* __restrict__ eb2,
                                                  const float* __restrict__ ea) {
    extern __shared__ char smem[];
    uint4* AF = reinterpret_cast<uint4*>(smem + TH_AF);
    uint32_t* stg = reinterpret_cast<uint32_t*>(smem + TH_STG);
    __half* ea16 = reinterpret_cast<__half*>(smem + TH_EA);
    __half* w1s = reinterpret_cast<__half*>(smem + TH_W1);
    float* b1s = reinterpret_cast<float*>(smem + TH_B1F);
    const int tid = threadIdx.x, warp = tid >> 5, lane = tid & 31;
    const int lq = lane >> 2, lr = lane & 3;
    const int m0 = blockIdx.x * 128;
    const uint32_t sb = smem_u32(smem);
    const int wg = warp & 3;
    const int wh = warp >> 2;
    const int wn = wh * 64;

    {
        const char* src = reinterpret_cast<const char*>(g_Bh);
#pragma unroll
        for (int it = 0; it < 8; it++) {
            int idx = it * 256 + tid;
            CP_ASYNC16(sb + TH_B0 + idx * 16, src + idx * 16);
        }
        CP_COMMIT();
#pragma unroll
        for (int it = 0; it < 8; it++) {
            int idx = it * 256 + tid;
            CP_ASYNC16(sb + TH_B1 + idx * 16, src + 32768 + idx * 16);
        }
        CP_COMMIT();
    }

    {
        int row = tid >> 1, half8 = tid & 1;
        float4 v0 = *reinterpret_cast<const float4*>(&ea[(size_t)(m0 + row) * EIN + half8 * 8]);
        float4 v1 = *reinterpret_cast<const float4*>(&ea[(size_t)(m0 + row) * EIN + half8 * 8 + 4]);
        uint32_t* dst = reinterpret_cast<uint32_t*>(&ea16[row * 24 + half8 * 8]);
        dst[0] = pack_h2(v0.x, v0.y);
        dst[1] = pack_h2(v0.z, v0.w);
        dst[2] = pack_h2(v1.x, v1.y);
        dst[3] = pack_h2(v1.z, v1.w);
    }
    for (int i = tid; i < 128 * 8; i += 256) {
        int n = i >> 3, q = i & 7;
        reinterpret_cast<uint32_t*>(&w1s[n * 24])[q] =
            reinterpret_cast<const uint32_t*>(&g_W1h[n * 16])[q];
    }
    if (tid < 128) b1s[tid] = g_b1f[tid];
    __syncthreads();

    // eh pass: A = relu(ea @ W1' + b1'), K=16; write fragment-native AF
    {
        float c0[2][8][4];
#pragma unroll
        for (int mt = 0; mt < 2; mt++)
#pragma unroll
            for (int nt = 0; nt < 8; nt++)
#pragma unroll
                for (int i = 0; i < 4; i++) c0[mt][nt][i] = 0.f;
        uint32_t a[2][4];
#pragma unroll
        for (int mt = 0; mt < 2; mt++) {
            int r = wg * 32 + mt * 16 + lq;
            a[mt][0] = *reinterpret_cast<const uint32_t*>(&ea16[r * 24 + lr * 2]);
            a[mt][1] = *reinterpret_cast<const uint32_t*>(&ea16[(r + 8) * 24 + lr * 2]);
            a[mt][2] = *reinterpret_cast<const uint32_t*>(&ea16[r * 24 + lr * 2 + 8]);
            a[mt][3] = *reinterpret_cast<const uint32_t*>(&ea16[(r + 8) * 24 + lr * 2 + 8]);
        }
#pragma unroll
        for (int nt = 0; nt < 8; nt++) {
            int n = wn + nt * 8 + lq;
            uint32_t b0 = *reinterpret_cast<const uint32_t*>(&w1s[n * 24 + lr * 2]);
            uint32_t b1 = *reinterpret_cast<const uint32_t*>(&w1s[n * 24 + lr * 2 + 8]);
            mma_f16_16x8x16(c0[0][nt], a[0], b0, b1);
            mma_f16_16x8x16(c0[1][nt], a[1], b0, b1);
        }
#pragma unroll
        for (int mt = 0; mt < 2; mt++) {
#pragma unroll
            for (int t = 0; t < 4; t++) {
                int nt0 = 2 * t, nt1 = 2 * t + 1;
                int col0 = wn + nt0 * 8 + lr * 2;
                int col1 = wn + nt1 * 8 + lr * 2;
                float b00 = b1s[col0], b01 = b1s[col0 + 1];
                float b10 = b1s[col1], b11 = b1s[col1 + 1];
                uint4 u;
                u.x = pack_h2(fmaxf(c0[mt][nt0][0] + b00, 0.f), fmaxf(c0[mt][nt0][1] + b01, 0.f));
                u.y = pack_h2(fmaxf(c0[mt][nt0][2] + b00, 0.f), fmaxf(c0[mt][nt0][3] + b01, 0.f));
                u.z = pack_h2(fmaxf(c0[mt][nt1][0] + b10, 0.f), fmaxf(c0[mt][nt1][1] + b11, 0.f));
                u.w = pack_h2(fmaxf(c0[mt][nt1][2] + b10, 0.f), fmaxf(c0[mt][nt1][3] + b11, 0.f));
                int mg = wg * 2 + mt;
                int ks = wh * 4 + t;
                AF[(mg * 8 + ks) * 32 + lane] = u;
            }
        }
    }
    CP_WAIT1();
    __syncthreads();

    const int mg0 = wg * 2;
    const int pairbar = 1 + wg;

#pragma unroll 1
    for (int p = 0; p < 8; p++) {
        const uint2* Bs = reinterpret_cast<const uint2*>(smem + ((p & 1) ? TH_B1 : TH_B0));

        float c[2][8][4];
#pragma unroll
        for (int mt = 0; mt < 2; mt++)
#pragma unroll
            for (int nt = 0; nt < 8; nt++)
#pragma unroll
                for (int i = 0; i < 4; i++) c[mt][nt][i] = 0.f;

#pragma unroll
        for (int ks = 0; ks < 8; ks++) {
            uint4 ua0 = AF[(mg0 * 8 + ks) * 32 + lane];
            uint4 ua1 = AF[((mg0 + 1) * 8 + ks) * 32 + lane];
            uint32_t a0[4] = {ua0.x, ua0.y, ua0.z, ua0.w};
            uint32_t a1[4] = {ua1.x, ua1.y, ua1.z, ua1.w};
#pragma unroll
            for (int nt = 0; nt < 8; nt++) {
                uint2 vb = Bs[(ks * 16 + wh * 8 + nt) * 32 + lane];
                mma_f16_16x8x16(c[0][nt], a0, vb.x, vb.y);
                mma_f16_16x8x16(c[1][nt], a1, vb.x, vb.y);
            }
        }

        // epilogue first (pair-local), overlapping the p+1 prefetch
#pragma unroll
        for (int mt = 0; mt < 2; mt++) {
#pragma unroll
            for (int nt = 0; nt < 8; nt++) {
                int col = wn + nt * 8 + lr * 2;
                float2 bv = __ldg(reinterpret_cast<const float2*>(&eb2[p * 128 + col]));
                uint32_t h0 = pack_h2(c[mt][nt][0] + bv.x, c[mt][nt][1] + bv.y);
                uint32_t h1 = pack_h2(c[mt][nt][2] + bv.x, c[mt][nt][3] + bv.y);
                int cch = wh * 8 + nt;
                int r0 = wg * 16 + lq;
                int r1 = r0 + 8;
                stg[r0 * 64 + ((cch ^ (r0 & 15)) << 2) + lr] = h0;
                stg[r1 * 64 + ((cch ^ (r1 & 15)) << 2) + lr] = h1;
            }
            BAR_PAIR(pairbar);
#pragma unroll
            for (int i = 0; i < 4; i++) {
                int idx = i * 32 + lane;
                int lrow8 = idx >> 4;
                int cch = idx & 15;
                int localRow = wg * 16 + wh * 8 + lrow8;
                uint4 v = *reinterpret_cast<const uint4*>(
                    &stg[localRow * 64 + ((cch ^ (localRow & 15)) << 2)]);
                int globalRow = m0 + wg * 32 + mt * 16 + wh * 8 + lrow8;
                reinterpret_cast<uint4*>(g_theta)[(size_t)globalRow * 128 + p * 16 + cch] = v;
            }
            BAR_PAIR(pairbar);
        }

        if (p < 7) CP_WAIT0();
        __syncthreads();

        if (p < 6) {
            uint32_t dstb = sb + ((p & 1) ? TH_B1 : TH_B0);
            const char* src = reinterpret_cast<const char*>(g_Bh) + (size_t)(p + 2) * 32768;
#pragma unroll
            for (int it = 0; it < 8; it++) {
                int idx = it * 256 + tid;
                CP_ASYNC16(dstb + idx * 16, src + idx * 16);
            }
            CP_COMMIT();
        }
    }
}

// ---------------- K5: msg = h[src] @ theta_e ; atomic scatter (uint4) -------
__global__ void __launch_bounds__(256) k_msg(const int* __restrict__ ei) {
    int gw = (blockIdx.x * blockDim.x + threadIdx.x) >> 5;
    if (gw >= N_EDGES) return;
    int lane = threadIdx.x & 31;
    int src = __ldg(&ei[gw]);
    int dst = __ldg(&ei[N_EDGES + gw]);
    float hv = g_h[src * D + lane];
    const uint4* th4 = reinterpret_cast<const uint4*>(g_theta + (size_t)gw * 512);
    const int colg = lane & 3;
    const int rbase = lane >> 2;
    float acc[8];
#pragma unroll
    for (int j = 0; j < 8; j++) acc[j] = 0.f;
#pragma unroll
    for (int it = 0; it < 4; it++) {
        int row = it * 8 + rbase;
        uint4 u = __ldcs(&th4[row * 4 + colg]);
        float hr = __shfl_sync(0xffffffffu, hv, row);
        float2 f0 = __half22float2(*reinterpret_cast<const __half2*>(&u.x));
        float2 f1 = __half22float2(*reinterpret_cast<const __half2*>(&u.y));
        float2 f2 = __half22float2(*reinterpret_cast<const __half2*>(&u.z));
        float2 f3 = __half22float2(*reinterpret_cast<const __half2*>(&u.w));
        acc[0] = fmaf(hr, f0.x, acc[0]); acc[1] = fmaf(hr, f0.y, acc[1]);
        acc[2] = fmaf(hr, f1.x, acc[2]); acc[3] = fmaf(hr, f1.y, acc[3]);
        acc[4] = fmaf(hr, f2.x, acc[4]); acc[5] = fmaf(hr, f2.y, acc[5]);
        acc[6] = fmaf(hr, f3.x, acc[6]); acc[7] = fmaf(hr, f3.y, acc[7]);
    }
#pragma unroll
    for (int m = 4; m <= 16; m <<= 1) {
#pragma unroll
        for (int j = 0; j < 8; j++)
            acc[j] += __shfl_xor_sync(0xffffffffu, acc[j], m);
    }
    if (lane < 4) {
        float* dp = &g_agg[dst * D + colg * 8];
#pragma unroll
        for (int j = 0; j < 8; j++) atomicAdd(dp + j, acc[j]);
    }
}

// ---------------- K6: conv + relu + GRU via HMMA, 128 nodes/block, occ 2 ----
#define UP_H16 0
#define UP_M16 (UP_H16 + 9216)
#define UP_W1  (UP_M16 + 9216)
#define UP_W2  (UP_W1 + 9216)
#define UP_HF  (UP_W2 + 6912)
#define UP_BIH (UP_HF + 18432)
#define UP_BHH (UP_BIH + 384)
#define UP_CB  (UP_BHH + 384)
#define UP_SMEM_TOTAL (UP_CB + 128)

__global__ void __launch_bounds__(256, 2) k_update(const float* __restrict__ cb,
                                                   const float* __restrict__ b_ih,
                                                   const float* __restrict__ b_hh,
                                                   float* __restrict__ out,
                                                   int write_out) {
    extern __shared__ char smem[];
    __half* h16 = reinterpret_cast<__half*>(smem + UP_H16);
    __half* m16 = reinterpret_cast<__half*>(smem + UP_M16);
    __half* w1 = reinterpret_cast<__half*>(smem + UP_W1);
    __half* w2 = reinterpret_cast<__half*>(smem + UP_W2);
    float* hf = reinterpret_cast<float*>(smem + UP_HF);
    float* sbih = reinterpret_cast<float*>(smem + UP_BIH);
    float* sbhh = reinterpret_cast<float*>(smem + UP_BHH);
    float* scb = reinterpret_cast<float*>(smem + UP_CB);
    const int tid = threadIdx.x, warp = tid >> 5, lane = tid & 31;
    const int lq = lane >> 2, lr = lane & 3;
    const int node0 = blockIdx.x * 128;
    const int wm = warp * 16;

    for (int i = tid; i < 128 * 32; i += 256) {
        int n = i >> 5, k = i & 31;
        w1[n * 36 + k] = g_Wcat[i];
    }
    for (int i = tid; i < 96 * 32; i += 256) {
        int n = i >> 5, k = i & 31;
        w2[n * 36 + k] = g_Wih[i];
    }
    if (tid < 96) { sbih[tid] = b_ih[tid]; sbhh[tid] = b_hh[tid]; }
    if (tid < 32) scb[tid] = cb[tid];

#pragma unroll
    for (int it = 0; it < 4; it++) {
        int idx = it * 256 + tid;
        int row = idx >> 3;
        int c4 = (idx & 7) << 2;
        int node = node0 + row;
        float4 v = make_float4(0.f, 0.f, 0.f, 0.f);
        if (node < N_NODES)
            v = *reinterpret_cast<const float4*>(&g_h[node * D + c4]);
        *reinterpret_cast<float4*>(&hf[row * 36 + c4]) = v;
        uint2 u = make_uint2(pack_h2(v.x, v.y), pack_h2(v.z, v.w));
        *reinterpret_cast<uint2*>(&h16[row * 36 + c4]) = u;
    }
    __syncthreads();

    float c1[16][4];
#pragma unroll
    for (int nt = 0; nt < 16; nt++)
#pragma unroll
        for (int i = 0; i < 4; i++) c1[nt][i] = 0.f;
#pragma unroll
    for (int ks = 0; ks < 2; ks++) {
        int kb = ks * 16 + lr * 2;
        uint32_t a[4];
        a[0] = *reinterpret_cast<const uint32_t*>(&h16[(wm + lq) * 36 + kb]);
        a[2] = *reinterpret_cast<const uint32_t*>(&h16[(wm + lq) * 36 + kb + 8]);
        a[1] = *reinterpret_cast<const uint32_t*>(&h16[(wm + lq + 8) * 36 + kb]);
        a[3] = *reinterpret_cast<const uint32_t*>(&h16[(wm + lq + 8) * 36 + kb + 8]);
#pragma unroll
        for (int nt = 0; nt < 16; nt++) {
            int n = nt * 8 + lq;
            uint32_t b0 = *reinterpret_cast<const uint32_t*>(&w1[n * 36 + kb]);
            uint32_t b1 = *reinterpret_cast<const uint32_t*>(&w1[n * 36 + kb + 8]);
            mma_f16_16x8x16(c1[nt], a, b0, b1);
        }
    }

    int rowA = wm + lq, rowB = wm + lq + 8;
    int nodeA = node0 + rowA, nodeB = node0 + rowB;
#pragma unroll
    for (int nt = 0; nt < 4; nt++) {
        int jp = nt * 8 + lr * 2;
        float cb0 = scb[jp], cb1 = scb[jp + 1];
        float2 agA = make_float2(0.f, 0.f), agB = make_float2(0.f, 0.f);
        if (nodeA < N_NODES) agA = *reinterpret_cast<const float2*>(&g_agg[nodeA * D + jp]);
        if (nodeB < N_NODES) agB = *reinterpret_cast<const float2*>(&g_agg[nodeB * D + jp]);
        float m0v = fmaxf(c1[12 + nt][0] + agA.x + cb0, 0.f);
        float m1v = fmaxf(c1[12 + nt][1] + agA.y + cb1, 0.f);
        float m2v = fmaxf(c1[12 + nt][2] + agB.x + cb0, 0.f);
        float m3v = fmaxf(c1[12 + nt][3] + agB.y + cb1, 0.f);
        *reinterpret_cast<uint32_t*>(&m16[rowA * 36 + jp]) = pack_h2(m0v, m1v);
        *reinterpret_cast<uint32_t*>(&m16[rowB * 36 + jp]) = pack_h2(m2v, m3v);
    }
    __syncthreads();

    float c2[12][4];
#pragma unroll
    for (int nt = 0; nt < 12; nt++)
#pragma unroll
        for (int i = 0; i < 4; i++) c2[nt][i] = 0.f;
#pragma unroll
    for (int ks = 0; ks < 2; ks++) {
        int kb = ks * 16 + lr * 2;
        uint32_t a[4];
        a[0] = *reinterpret_cast<const uint32_t*>(&m16[(wm + lq) * 36 + kb]);
        a[2] = *reinterpret_cast<const uint32_t*>(&m16[(wm + lq) * 36 + kb + 8]);
        a[1] = *reinterpret_cast<const uint32_t*>(&m16[(wm + lq + 8) * 36 + kb]);
        a[3] = *reinterpret_cast<const uint32_t*>(&m16[(wm + lq + 8) * 36 + kb + 8]);
#pragma unroll
        for (int nt = 0; nt < 12; nt++) {
            int n = nt * 8 + lq;
            uint32_t b0 = *reinterpret_cast<const uint32_t*>(&w2[n * 36 + kb]);
            uint32_t b1 = *reinterpret_cast<const uint32_t*>(&w2[n * 36 + kb + 8]);
            mma_f16_16x8x16(c2[nt], a, b0, b1);
        }
    }

#pragma unroll
    for (int nt = 0; nt < 4; nt++) {
        int jp = nt * 8 + lr * 2;
#pragma unroll
        for (int hrow = 0; hrow < 2; hrow++) {
            int node = hrow ? nodeB : nodeA;
            if (node >= N_NODES) continue;
            int rl = hrow ? rowB : rowA;
            float hn0, hn1;
            {
                int ci = 2 * hrow;
                float gr0 = c2[nt][ci] + sbih[jp] + c1[nt][ci] + sbhh[jp];
                float gr1 = c2[nt][ci + 1] + sbih[jp + 1] + c1[nt][ci + 1] + sbhh[jp + 1];
                float gz0 = c2[4 + nt][ci] + sbih[32 + jp] + c1[4 + nt][ci] + sbhh[32 + jp];
                float gz1 = c2[4 + nt][ci + 1] + sbih[33 + jp] + c1[4 + nt][ci + 1] + sbhh[33 + jp];
                float r0 = fsig(gr0);
                float r1 = fsig(gr1);
                float z0 = fsig(gz0);
                float z1 = fsig(gz1);
                float gn0 = c2[8 + nt][ci] + sbih[64 + jp];
                float gn1 = c2[8 + nt][ci + 1] + sbih[65 + jp];
                float ghn0 = c1[8 + nt][ci] + sbhh[64 + jp];
                float ghn1 = c1[8 + nt][ci + 1] + sbhh[65 + jp];
                float n0 = ftanh(gn0 + r0 * ghn0);
                float n1 = ftanh(gn1 + r1 * ghn1);
                float hv0 = hf[rl * 36 + jp];
                float hv1 = hf[rl * 36 + jp + 1];
                hn0 = (1.f - z0) * n0 + z0 * hv0;
                hn1 = (1.f - z1) * n1 + z1 * hv1;
            }
            float2 hv2 = make_float2(hn0, hn1);
            *reinterpret_cast<float2*>(&g_h[node * D + jp]) = hv2;
            *reinterpret_cast<float2*>(&g_agg[node * D + jp]) = make_float2(0.f, 0.f);
            if (write_out)
                *reinterpret_cast<float2*>(&out[node * D + jp]) = hv2;
        }
    }
}

// ---------------- launch ----------------
extern "C" void kernel_launch(void* const* d_in, const int* in_sizes, int n_in,
                              void* d_out, int out_size) {
    (void)in_sizes; (void)n_in; (void)out_size;
    const float* x        = (const float*)d_in[0];
    const int*   ei       = (const int*)d_in[1];
    const float* ea       = (const float*)d_in[2];
    const float* proj_W   = (const float*)d_in[3];
    const float* proj_b   = (const float*)d_in[4];
    const float* bn1_g    = (const float*)d_in[5];
    const float* bn1_b    = (const float*)d_in[6];
    const float* eW1      = (const float*)d_in[7];
    const float* eb1      = (const float*)d_in[8];
    const float* bn2_g    = (const float*)d_in[9];
    const float* bn2_b    = (const float*)d_in[10];
    const float* eW2      = (const float*)d_in[11];
    const float* eb2      = (const float*)d_in[12];
    const float* root     = (const float*)d_in[13];
    const float* cb       = (const float*)d_in[14];
    const float* W_ih     = (const float*)d_in[15];
    const float* W_hh     = (const float*)d_in[16];
    const float* b_ih     = (const float*)d_in[17];
    const float* b_hh     = (const float*)d_in[18];
    float* out = (float*)d_out;

    static int attr_set = 0;
    if (!attr_set) {
        cudaFuncSetAttribute(k_theta, cudaFuncAttributeMaxDynamicSharedMemorySize,
                             TH_SMEM_TOTAL);
        cudaFuncSetAttribute(k_update, cudaFuncAttributeMaxDynamicSharedMemorySize,
                             UP_SMEM_TOTAL);
        attr_set = 1;
    }

    // fused prologue: proj (5000 blocks) + prepB (128) + prepW (1)
    k_pre<<<5129, 256>>>(x, proj_W, proj_b, bn1_g, bn1_b, eW2,
                         W_hh, root, W_ih, eW1, eb1, bn2_g, bn2_b);
    k_theta<<<N_EDGES / 128, 256, TH_SMEM_TOTAL>>>(eb2, ea);

    for (int s = 0; s < STEPS; s++) {
        k_msg<<<N_EDGES * 32 / 256, 256>>>(ei);
        k_update<<<(N_NODES + 127) / 128, 256, UP_SMEM_TOTAL>>>(
            cb, b_ih, b_hh, out, s == STEPS - 1 ? 1 : 0);
    }
}